// round 2
// baseline (speedup 1.0000x reference)
#include <cuda_runtime.h>

#define T_STEPS 512
#define BATCH   256
#define HDIM    256
#define N3H     768
#define NCTA    128   // recurrent grid (8 batch-tiles x 16 col-tiles)

// Scratch (no cudaMalloc allowed): gi buffer [T,B,3H], double-buffered h state,
// grid barrier counter, resets-dtype flag.
__device__ float    g_gi[(size_t)T_STEPS * BATCH * N3H];   // 384 MB
__device__ float    g_h0[BATCH * HDIM];
__device__ float    g_h1[BATCH * HDIM];
__device__ unsigned g_bar;
__device__ int      g_rst_is_int;

// ---------------------------------------------------------------------------
// Detect whether `resets` is int32 (harness-promoted bool) or raw uint8.
// For int32 data, every byte at offset i%4!=0 within the first 131072 bytes is
// zero; for uint8 bool data ~50% of them are 1. Single block, deterministic.
// ---------------------------------------------------------------------------
__global__ void detect_reset_dtype(const unsigned char* __restrict__ r) {
    __shared__ int found;
    if (threadIdx.x == 0) found = 0;
    __syncthreads();
    int nz = 0;
    for (int i = threadIdx.x; i < T_STEPS * BATCH; i += blockDim.x) {
        if ((i & 3) != 0 && r[i] != 0) nz = 1;
    }
    if (nz) atomicOr(&found, 1);
    __syncthreads();
    if (threadIdx.x == 0) g_rst_is_int = (found == 0) ? 1 : 0;
}

// ---------------------------------------------------------------------------
// init: reset barrier counter + h state every launch (graph-replay safe)
// ---------------------------------------------------------------------------
__global__ void init_state(const float* __restrict__ carry) {
    int i = blockIdx.x * blockDim.x + threadIdx.x;
    if (i == 0) g_bar = 0u;
    if (i < BATCH * HDIM) g_h0[i] = carry[i];
}

// ---------------------------------------------------------------------------
// gi = X @ Wi + bi : [131072,256] x [256,768]
// BM=128 BN=64 BK=16, 256 threads, 8x4 microtile
// ---------------------------------------------------------------------------
__global__ __launch_bounds__(256, 2) void gi_gemm(
    const float* __restrict__ X, const float* __restrict__ Wi,
    const float* __restrict__ bi)
{
    __shared__ float As[16 * 132];  // [k][m], padded
    __shared__ float Bs[16 * 68];   // [k][n], padded

    const int nt = blockIdx.x % 12;
    const int mt = blockIdx.x / 12;           // consecutive bids share A tile (L2 reuse)
    const int m0 = mt * 128, n0 = nt * 64;
    const int tid = threadIdx.x;
    const int tx = tid & 15, ty = tid >> 4;

    float acc[8][4];
    #pragma unroll
    for (int i = 0; i < 8; ++i)
        #pragma unroll
        for (int j = 0; j < 4; ++j) acc[i][j] = 0.f;

    for (int kk = 0; kk < 256; kk += 16) {
        #pragma unroll
        for (int r = 0; r < 2; ++r) {
            int f = tid + 256 * r;            // 512 float4 of A tile
            int row = f >> 2, c4 = f & 3;
            float4 v = *reinterpret_cast<const float4*>(
                &X[(size_t)(m0 + row) * 256 + kk + c4 * 4]);
            As[(c4*4+0)*132 + row] = v.x;
            As[(c4*4+1)*132 + row] = v.y;
            As[(c4*4+2)*132 + row] = v.z;
            As[(c4*4+3)*132 + row] = v.w;
        }
        {
            int row = tid >> 4, c4 = tid & 15;
            float4 v = *reinterpret_cast<const float4*>(
                &Wi[(size_t)(kk + row) * 768 + n0 + c4 * 4]);
            *reinterpret_cast<float4*>(&Bs[row * 68 + c4 * 4]) = v;
        }
        __syncthreads();
        #pragma unroll
        for (int k = 0; k < 16; ++k) {
            float4 a0 = *reinterpret_cast<const float4*>(&As[k*132 + ty*8]);
            float4 a1 = *reinterpret_cast<const float4*>(&As[k*132 + ty*8 + 4]);
            float4 b0 = *reinterpret_cast<const float4*>(&Bs[k*68 + tx*4]);
            float a[8] = {a0.x,a0.y,a0.z,a0.w,a1.x,a1.y,a1.z,a1.w};
            float b[4] = {b0.x,b0.y,b0.z,b0.w};
            #pragma unroll
            for (int i = 0; i < 8; ++i)
                #pragma unroll
                for (int j = 0; j < 4; ++j)
                    acc[i][j] += a[i] * b[j];
        }
        __syncthreads();
    }

    float4 bias = *reinterpret_cast<const float4*>(&bi[n0 + tx*4]);
    #pragma unroll
    for (int i = 0; i < 8; ++i) {
        float4 o;
        o.x = acc[i][0] + bias.x; o.y = acc[i][1] + bias.y;
        o.z = acc[i][2] + bias.z; o.w = acc[i][3] + bias.w;
        *reinterpret_cast<float4*>(
            &g_gi[(size_t)(m0 + ty*8 + i) * 768 + n0 + tx*4]) = o;
    }
}

// ---------------------------------------------------------------------------
// Persistent recurrent scan. Grid = 128 CTAs = 8 batch-tiles(32) x 16 col-tiles
// (16 cols per gate). Wh slice pinned in smem; double-buffered h state in
// global (no intra-step read/write race); one grid barrier per step.
// ---------------------------------------------------------------------------
__global__ __launch_bounds__(384, 1) void rnn_scan(
    const void* __restrict__ resets_raw,
    const float* __restrict__ Wh,
    const float* __restrict__ bhn,
    float* __restrict__ ys)
{
    extern __shared__ float sm[];
    float* whs = sm;                    // [256][48]  (48 = 3 gates x 16 cols)
    float* hs  = sm + 12288;            // [32][257]  padded h tile
    float* ghs = sm + 12288 + 8224;     // [3][32][17] gh exchange

    const int tid = threadIdx.x;
    const int cb  = blockIdx.x & 7;     // batch tile
    const int cj  = blockIdx.x >> 3;    // column tile
    const int B0  = cb * 32;
    const int j0  = cj * 16;

    const bool rst_is_int = (g_rst_is_int != 0);
    const int* __restrict__ rst_i = (const int*)resets_raw;
    const unsigned char* __restrict__ rst_b = (const unsigned char*)resets_raw;

    // Load Wh slice once: whs[k][g*16+jj] = Wh[k][g*256 + j0 + jj]
    for (int i = tid; i < 256 * 48; i += 384) {
        int k = i / 48, c = i - k * 48;
        int g = c >> 4, jj = c & 15;
        whs[i] = Wh[(size_t)k * 768 + g * 256 + j0 + jj];
    }

    const int warp = tid >> 5, lane = tid & 31;
    const int wb = warp & 3, wg = warp >> 2;   // warp: 8 b-rows, one gate (16 j)
    const int lb = lane >> 3, lj = lane & 7;   // lane: 2 b x 2 j
    const int bA = wb * 8 + lb * 2;
    const int jc = wg * 16 + lj * 2;

    // elementwise work items: i0 = tid (<384), i1 = tid+384 (tid<128)
    const int e0b = tid >> 4,         e0j = tid & 15;
    const int e1b = (tid + 384) >> 4, e1j = (tid + 384) & 15;
    const float bhn0 = bhn[j0 + e0j];
    const float bhn1 = (tid < 128) ? bhn[j0 + e1j] : 0.f;

    for (int t = 0; t < T_STEPS; ++t) {
        const float* __restrict__ hsrc = (t & 1) ? g_h1 : g_h0;
        float*       __restrict__ hdst = (t & 1) ? g_h0 : g_h1;

        // ---- load h tile from global (L2-coherent), apply reset mask ----
        const int rbase = t * BATCH + B0;
        for (int i = tid; i < 32 * 64; i += 384) {
            int b = i >> 6, k4 = i & 63;
            float4 v = __ldcg(reinterpret_cast<const float4*>(
                &hsrc[(B0 + b) * 256 + k4 * 4]));
            bool rz = rst_is_int ? (rst_i[rbase + b] != 0)
                                 : (rst_b[rbase + b] != 0);
            if (rz) { v.x = 0.f; v.y = 0.f; v.z = 0.f; v.w = 0.f; }
            float* d = &hs[b * 257 + k4 * 4];
            d[0] = v.x; d[1] = v.y; d[2] = v.z; d[3] = v.w;
        }
        // ---- prefetch gi for elementwise phase (hides L2 latency) ----
        const float* gibase = g_gi + (size_t)(t * BATCH + B0) * 768 + j0;
        float gr0, gz0, gn0, gr1 = 0.f, gz1 = 0.f, gn1 = 0.f;
        {
            const float* p = gibase + (size_t)e0b * 768 + e0j;
            gr0 = p[0]; gz0 = p[256]; gn0 = p[512];
            if (tid < 128) {
                const float* q = gibase + (size_t)e1b * 768 + e1j;
                gr1 = q[0]; gz1 = q[256]; gn1 = q[512];
            }
        }
        __syncthreads();

        // ---- gh = h @ Wh  (warp-broadcast FFMA GEMM) ----
        float a00 = 0.f, a01 = 0.f, a10 = 0.f, a11 = 0.f;
        #pragma unroll 16
        for (int k = 0; k < 256; ++k) {
            float2 w  = *reinterpret_cast<const float2*>(&whs[k * 48 + jc]);
            float  h0 = hs[bA * 257 + k];
            float  h1 = hs[(bA + 1) * 257 + k];
            a00 += h0 * w.x; a01 += h0 * w.y;
            a10 += h1 * w.x; a11 += h1 * w.y;
        }
        ghs[wg * 544 + bA * 17 + lj * 2]           = a00;
        ghs[wg * 544 + bA * 17 + lj * 2 + 1]       = a01;
        ghs[wg * 544 + (bA + 1) * 17 + lj * 2]     = a10;
        ghs[wg * 544 + (bA + 1) * 17 + lj * 2 + 1] = a11;
        __syncthreads();

        // ---- gates + state update ----
        {
            float rr   = ghs[e0b * 17 + e0j];
            float zz   = ghs[544 + e0b * 17 + e0j];
            float nn   = ghs[1088 + e0b * 17 + e0j];
            float hold = hs[e0b * 257 + j0 + e0j];
            float r = 1.f / (1.f + expf(-(gr0 + rr)));
            float z = 1.f / (1.f + expf(-(gz0 + zz)));
            float n = tanhf(gn0 + r * (nn + bhn0));
            float hnew = (1.f - z) * n + z * hold;
            ys[(size_t)(t * BATCH + B0 + e0b) * 256 + j0 + e0j] = hnew;
            hdst[(B0 + e0b) * 256 + j0 + e0j] = hnew;
        }
        if (tid < 128) {
            float rr   = ghs[e1b * 17 + e1j];
            float zz   = ghs[544 + e1b * 17 + e1j];
            float nn   = ghs[1088 + e1b * 17 + e1j];
            float hold = hs[e1b * 257 + j0 + e1j];
            float r = 1.f / (1.f + expf(-(gr1 + rr)));
            float z = 1.f / (1.f + expf(-(gz1 + zz)));
            float n = tanhf(gn1 + r * (nn + bhn1));
            float hnew = (1.f - z) * n + z * hold;
            ys[(size_t)(t * BATCH + B0 + e1b) * 256 + j0 + e1j] = hnew;
            hdst[(B0 + e1b) * 256 + j0 + e1j] = hnew;
        }

        // ---- grid barrier (all 128 CTAs co-resident: grid <= SM count) ----
        if (t < T_STEPS - 1) {
            __threadfence();
            __syncthreads();
            if (tid == 0) {
                unsigned target = (unsigned)NCTA * (unsigned)(t + 1);
                atomicAdd(&g_bar, 1u);
                while (*(volatile unsigned*)&g_bar < target) { }
                __threadfence();
            }
            __syncthreads();
        }
    }
}

// ---------------------------------------------------------------------------
extern "C" void kernel_launch(void* const* d_in, const int* in_sizes, int n_in,
                              void* d_out, int out_size) {
    const float* ins    = (const float*)d_in[0];   // [512,256,256]
    const void*  resets = d_in[1];                 // [512,256] bool (int32 or u8)
    const float* carry  = (const float*)d_in[2];   // [256,256]
    const float* Wi     = (const float*)d_in[3];   // [256,768]
    const float* bi     = (const float*)d_in[4];   // [768]
    const float* Wh     = (const float*)d_in[5];   // [256,768]
    const float* bhn    = (const float*)d_in[6];   // [256]
    float*       ys     = (float*)d_out;           // [512,256,256]

    (void)in_sizes; (void)n_in; (void)out_size;

    cudaFuncSetAttribute(rnn_scan, cudaFuncAttributeMaxDynamicSharedMemorySize,
                         90112);

    detect_reset_dtype<<<1, 256>>>((const unsigned char*)resets);
    init_state<<<256, 256>>>(carry);
    gi_gemm<<<12288, 256>>>(ins, Wi, bi);
    rnn_scan<<<NCTA, 384, 88576>>>(resets, Wh, bhn, ys);
}

// round 6
// speedup vs baseline: 1.8155x; 1.8155x over previous
#include <cuda_runtime.h>

#define T_STEPS 512
#define BATCH   256
#define HDIM    256
#define N3H     768
#define NCTA    128   // 8 batch-tiles x 16 col-tiles

// Scratch: gi buffer, double-buffered h, per-btile barriers, dtype flag.
__device__ float    g_gi[(size_t)T_STEPS * BATCH * N3H];
__device__ float    g_h0[BATCH * HDIM];
__device__ float    g_h1[BATCH * HDIM];
__device__ unsigned g_bar[256];          // 8 counters, 128B apart
__device__ int      g_rst_is_int;

// ---------------------------------------------------------------------------
__global__ void detect_reset_dtype(const unsigned char* __restrict__ r) {
    __shared__ int found;
    if (threadIdx.x == 0) found = 0;
    __syncthreads();
    int nz = 0;
    for (int i = threadIdx.x; i < T_STEPS * BATCH; i += blockDim.x)
        if ((i & 3) != 0 && r[i] != 0) nz = 1;
    if (nz) atomicOr(&found, 1);
    __syncthreads();
    if (threadIdx.x == 0) g_rst_is_int = (found == 0) ? 1 : 0;
}

__global__ void init_state(const float* __restrict__ carry) {
    int i = blockIdx.x * blockDim.x + threadIdx.x;
    if (i < 256) g_bar[i] = 0u;
    if (i < BATCH * HDIM) g_h0[i] = carry[i];
}

// ---------------------------------------------------------------------------
// gi = X @ Wi + bi : [131072,256] x [256,768]  (unchanged, ~fp32 floor)
// ---------------------------------------------------------------------------
__global__ __launch_bounds__(256, 2) void gi_gemm(
    const float* __restrict__ X, const float* __restrict__ Wi,
    const float* __restrict__ bi)
{
    __shared__ float As[16 * 132];
    __shared__ float Bs[16 * 68];

    const int nt = blockIdx.x % 12;
    const int mt = blockIdx.x / 12;
    const int m0 = mt * 128, n0 = nt * 64;
    const int tid = threadIdx.x;
    const int tx = tid & 15, ty = tid >> 4;

    float acc[8][4];
    #pragma unroll
    for (int i = 0; i < 8; ++i)
        #pragma unroll
        for (int j = 0; j < 4; ++j) acc[i][j] = 0.f;

    for (int kk = 0; kk < 256; kk += 16) {
        #pragma unroll
        for (int r = 0; r < 2; ++r) {
            int f = tid + 256 * r;
            int row = f >> 2, c4 = f & 3;
            float4 v = *reinterpret_cast<const float4*>(
                &X[(size_t)(m0 + row) * 256 + kk + c4 * 4]);
            As[(c4*4+0)*132 + row] = v.x;
            As[(c4*4+1)*132 + row] = v.y;
            As[(c4*4+2)*132 + row] = v.z;
            As[(c4*4+3)*132 + row] = v.w;
        }
        {
            int row = tid >> 4, c4 = tid & 15;
            float4 v = *reinterpret_cast<const float4*>(
                &Wi[(size_t)(kk + row) * 768 + n0 + c4 * 4]);
            *reinterpret_cast<float4*>(&Bs[row * 68 + c4 * 4]) = v;
        }
        __syncthreads();
        #pragma unroll
        for (int k = 0; k < 16; ++k) {
            float4 a0 = *reinterpret_cast<const float4*>(&As[k*132 + ty*8]);
            float4 a1 = *reinterpret_cast<const float4*>(&As[k*132 + ty*8 + 4]);
            float4 b0 = *reinterpret_cast<const float4*>(&Bs[k*68 + tx*4]);
            float a[8] = {a0.x,a0.y,a0.z,a0.w,a1.x,a1.y,a1.z,a1.w};
            float b[4] = {b0.x,b0.y,b0.z,b0.w};
            #pragma unroll
            for (int i = 0; i < 8; ++i)
                #pragma unroll
                for (int j = 0; j < 4; ++j)
                    acc[i][j] += a[i] * b[j];
        }
        __syncthreads();
    }

    float4 bias = *reinterpret_cast<const float4*>(&bi[n0 + tx*4]);
    #pragma unroll
    for (int i = 0; i < 8; ++i) {
        float4 o;
        o.x = acc[i][0] + bias.x; o.y = acc[i][1] + bias.y;
        o.z = acc[i][2] + bias.z; o.w = acc[i][3] + bias.w;
        *reinterpret_cast<float4*>(
            &g_gi[(size_t)(m0 + ty*8 + i) * 768 + n0 + tx*4]) = o;
    }
}

// ---------------------------------------------------------------------------
// Smem layout (floats):
//   whs [256][48]          @ 0        (12288)
//   hs  [32][260]          @ 12288    (8320)   row-major h tile, padded
//   ghs [3][32][18]        @ 20608    (1728)   gh exchange, padded
//   red [3][96][18]        @ 22336    (5184)   split-k partials
#define SM_HS   12288
#define SM_GHS  20608
#define SM_RED  22336
#define SM_FLOATS (22336 + 5184)

__device__ __forceinline__ void bar_arrive(unsigned* p) {
    asm volatile("red.release.gpu.global.add.u32 [%0], %1;"
                 :: "l"(p), "r"(1u) : "memory");
}
__device__ __forceinline__ unsigned bar_peek(unsigned* p) {
    unsigned v;
    asm volatile("ld.acquire.gpu.global.u32 %0, [%1];"
                 : "=r"(v) : "l"(p) : "memory");
    return v;
}

__global__ __launch_bounds__(384, 1) void rnn_scan(
    const void* __restrict__ resets_raw,
    const float* __restrict__ Wh,
    const float* __restrict__ bhn,
    float* __restrict__ ys)
{
    extern __shared__ float sm[];
    float* whs = sm;
    float* hs  = sm + SM_HS;
    float* ghs = sm + SM_GHS;
    float* red = sm + SM_RED;

    const int tid = threadIdx.x;
    const int cb  = blockIdx.x & 7;
    const int cj  = blockIdx.x >> 3;
    const int B0  = cb * 32;
    const int j0  = cj * 16;
    unsigned* mybar = &g_bar[cb * 32];

    const bool rst_is_int = (g_rst_is_int != 0);
    const int* __restrict__ rst_i = (const int*)resets_raw;
    const unsigned char* __restrict__ rst_b = (const unsigned char*)resets_raw;

    // Wh slice: whs[k][g*16+jj] = Wh[k][g*256 + j0 + jj]
    for (int i = tid; i < 256 * 48; i += 384) {
        int k = i / 48, c = i - k * 48;
        int g = c >> 4, jj = c & 15;
        whs[i] = Wh[(size_t)k * 768 + g * 256 + j0 + jj];
    }

    // GEMM thread map: 96 output-threads (8b x 2j each) x 4 k-quarters
    const int to = tid % 96;
    const int kq = tid / 96;               // 0..3
    const int ob = (to / 24) * 8;          // 0,8,16,24
    const int oj = (to % 24) * 2;          // 0..46 even
    const int k0 = kq * 64;
    const int gg = oj >> 4, jj0 = oj & 15;

    // elementwise map: e0 = tid, e1 = tid+384 (tid<128)
    const int e0b = tid >> 4,         e0j = tid & 15;
    const int e1b = (tid + 384) >> 4, e1j = (tid + 384) & 15;
    const float bhn0 = bhn[j0 + e0j];
    const float bhn1 = (tid < 128) ? bhn[j0 + e1j] : 0.f;

    for (int t = 0; t < T_STEPS; ++t) {
        const float* __restrict__ hsrc = (t & 1) ? g_h1 : g_h0;
        float*       __restrict__ hdst = (t & 1) ? g_h0 : g_h1;

        // ---- load + reset-mask h tile ----
        const int rbase = t * BATCH + B0;
        for (int i = tid; i < 32 * 64; i += 384) {
            int b = i >> 6, k4 = i & 63;
            float4 v = __ldcg(reinterpret_cast<const float4*>(
                &hsrc[(B0 + b) * 256 + k4 * 4]));
            bool rz = rst_is_int ? (rst_i[rbase + b] != 0)
                                 : (rst_b[rbase + b] != 0);
            if (rz) { v.x = 0.f; v.y = 0.f; v.z = 0.f; v.w = 0.f; }
            *reinterpret_cast<float4*>(&hs[b * 260 + k4 * 4]) = v;
        }
        // ---- prefetch gi (consumed after GEMM; DRAM latency hidden) ----
        const float* gibase = g_gi + (size_t)(t * BATCH + B0) * 768 + j0;
        float gr0, gz0, gn0, gr1 = 0.f, gz1 = 0.f, gn1 = 0.f;
        {
            const float* p = gibase + (size_t)e0b * 768 + e0j;
            gr0 = p[0]; gz0 = p[256]; gn0 = p[512];
            if (tid < 128) {
                const float* q = gibase + (size_t)e1b * 768 + e1j;
                gr1 = q[0]; gz1 = q[256]; gn1 = q[512];
            }
        }
        __syncthreads();

        // ---- gh = h @ Wh : 8b x 2j per thread, split-k-4 ----
        float acc[8][2];
        #pragma unroll
        for (int i = 0; i < 8; ++i) { acc[i][0] = 0.f; acc[i][1] = 0.f; }

        #pragma unroll 4
        for (int k2 = 0; k2 < 64; k2 += 2) {
            int k = k0 + k2;
            float2 wA = *reinterpret_cast<const float2*>(&whs[k * 48 + oj]);
            float2 wB = *reinterpret_cast<const float2*>(&whs[(k + 1) * 48 + oj]);
            #pragma unroll
            for (int i = 0; i < 8; ++i) {
                float2 h2 = *reinterpret_cast<const float2*>(&hs[(ob + i) * 260 + k]);
                acc[i][0] += h2.x * wA.x;
                acc[i][1] += h2.x * wA.y;
                acc[i][0] += h2.y * wB.x;
                acc[i][1] += h2.y * wB.y;
            }
        }
        if (kq != 0) {
            float* r = &red[(kq - 1) * 1728 + to * 18];
            #pragma unroll
            for (int i = 0; i < 8; ++i)
                *reinterpret_cast<float2*>(&r[i * 2]) =
                    make_float2(acc[i][0], acc[i][1]);
        }
        __syncthreads();
        if (kq == 0) {
            const float* r1 = &red[to * 18];
            const float* r2 = &red[1728 + to * 18];
            const float* r3 = &red[3456 + to * 18];
            #pragma unroll
            for (int i = 0; i < 8; ++i) {
                float s0 = acc[i][0] + r1[i*2]   + r2[i*2]   + r3[i*2];
                float s1 = acc[i][1] + r1[i*2+1] + r2[i*2+1] + r3[i*2+1];
                *reinterpret_cast<float2*>(&ghs[gg * 576 + (ob + i) * 18 + jj0]) =
                    make_float2(s0, s1);
            }
        }
        __syncthreads();

        // ---- gates + state update ----
        float y0, y1 = 0.f;
        {
            float rr   = ghs[e0b * 18 + e0j];
            float zz   = ghs[576 + e0b * 18 + e0j];
            float nn   = ghs[1152 + e0b * 18 + e0j];
            float hold = hs[e0b * 260 + j0 + e0j];
            float r = 1.f / (1.f + __expf(-(gr0 + rr)));
            float z = 1.f / (1.f + __expf(-(gz0 + zz)));
            float targ = gn0 + r * (nn + bhn0);
            float e = __expf(-2.f * targ);
            float n = (1.f - e) / (1.f + e);
            y0 = (1.f - z) * n + z * hold;
            hdst[(B0 + e0b) * 256 + j0 + e0j] = y0;
        }
        if (tid < 128) {
            float rr   = ghs[e1b * 18 + e1j];
            float zz   = ghs[576 + e1b * 18 + e1j];
            float nn   = ghs[1152 + e1b * 18 + e1j];
            float hold = hs[e1b * 260 + j0 + e1j];
            float r = 1.f / (1.f + __expf(-(gr1 + rr)));
            float z = 1.f / (1.f + __expf(-(gz1 + zz)));
            float targ = gn1 + r * (nn + bhn1);
            float e = __expf(-2.f * targ);
            float n = (1.f - e) / (1.f + e);
            y1 = (1.f - z) * n + z * hold;
            hdst[(B0 + e1b) * 256 + j0 + e1j] = y1;
        }

        // ---- per-btile barrier: arrive, then ys stores, then wait ----
        __syncthreads();                      // hdst stores done CTA-wide
        if (t < T_STEPS - 1) {
            if (tid == 0) bar_arrive(mybar);
            ys[(size_t)(t * BATCH + B0 + e0b) * 256 + j0 + e0j] = y0;
            if (tid < 128)
                ys[(size_t)(t * BATCH + B0 + e1b) * 256 + j0 + e1j] = y1;
            if (tid == 0) {
                unsigned target = 16u * (unsigned)(t + 1);
                while (bar_peek(mybar) < target) { }
            }
            __syncthreads();
        } else {
            ys[(size_t)(t * BATCH + B0 + e0b) * 256 + j0 + e0j] = y0;
            if (tid < 128)
                ys[(size_t)(t * BATCH + B0 + e1b) * 256 + j0 + e1j] = y1;
        }
    }
}

// ---------------------------------------------------------------------------
extern "C" void kernel_launch(void* const* d_in, const int* in_sizes, int n_in,
                              void* d_out, int out_size) {
    const float* ins    = (const float*)d_in[0];
    const void*  resets = d_in[1];
    const float* carry  = (const float*)d_in[2];
    const float* Wi     = (const float*)d_in[3];
    const float* bi     = (const float*)d_in[4];
    const float* Wh     = (const float*)d_in[5];
    const float* bhn    = (const float*)d_in[6];
    float*       ys     = (float*)d_out;

    (void)in_sizes; (void)n_in; (void)out_size;

    cudaFuncSetAttribute(rnn_scan, cudaFuncAttributeMaxDynamicSharedMemorySize,
                         SM_FLOATS * 4);

    detect_reset_dtype<<<1, 256>>>((const unsigned char*)resets);
    init_state<<<256, 256>>>(carry);
    gi_gemm<<<12288, 256>>>(ins, Wi, bi);
    rnn_scan<<<NCTA, 384, SM_FLOATS * 4>>>(resets, Wh, bhn, ys);
}